// round 1
// baseline (speedup 1.0000x reference)
#include <cuda_runtime.h>
#include <cstdint>

#define LOG2E 1.4426950408889634f

// ---------------- scratch (device globals; no allocations allowed) ----------
__device__ float g_xsum[64];
__device__ float g_t[64];                 // relu(MLP) * log2(e)
__device__ float g_Wc[64 * 25 * 9];       // composed weights, layout [i][tap][k]
__device__ float g_bc[9 * 25];            // per-tap bias contribution [k][tap]
__device__ float g_bfield[9 * 128 * 128]; // clipped bias field [k][h][w]
__device__ float g_wt[8 * 9 * 128 * 128]; // conv output logits [b][k][h][w]

// ---------------- kernel A: per-channel sum of x (for consensus mean) -------
__global__ void k_chansum(const float* __restrict__ x) {
    int c = blockIdx.x;
    int tid = threadIdx.x;
    float s = 0.f;
    for (int b = 0; b < 8; ++b) {
        const float4* p = (const float4*)(x + (size_t)(b * 64 + c) * 16384);
        for (int i = tid; i < 4096; i += 256) {
            float4 v = p[i];
            s += v.x + v.y + v.z + v.w;
        }
    }
    __shared__ float sh[256];
    sh[tid] = s;
    __syncthreads();
    for (int o = 128; o > 0; o >>= 1) {
        if (tid < o) sh[tid] += sh[tid + o];
        __syncthreads();
    }
    if (tid == 0) g_xsum[c] = sh[0];
}

// ---------------- kernel B: consensus MLP -> g_t ----------------------------
__global__ void k_mlp(const float* __restrict__ tc1, const float* __restrict__ tc2) {
    __shared__ float smean[64];
    __shared__ float sh1[16];
    int tid = threadIdx.x;  // 64 threads
    smean[tid] = g_xsum[tid] * (1.f / 131072.f);
    __syncthreads();
    if (tid < 16) {
        float a = 0.f;
        #pragma unroll
        for (int c = 0; c < 64; ++c) a += tc1[tid * 64 + c] * smean[c];
        sh1[tid] = fmaxf(a, 0.f);
    }
    __syncthreads();
    float a = 0.f;
    #pragma unroll
    for (int j = 0; j < 16; ++j) a += tc2[tid * 16 + j] * sh1[j];
    g_t[tid] = fmaxf(a, 0.f) * LOG2E;
}

// ---------------- kernel C: compose 1x1 conv into 5x5 conv ------------------
// Wc[k,i,tap] = sum_o w2[k,o,tap] * w1[o,i];  bc[k,tap] = sum_o w2[k,o,tap]*b1[o]
__global__ void k_weights(const float* __restrict__ w1, const float* __restrict__ b1,
                          const float* __restrict__ w2) {
    int idx = blockIdx.x * blockDim.x + threadIdx.x;
    if (idx < 14400) {
        int k = idx / 1600, rem = idx % 1600;
        int i = rem / 25, tap = rem % 25;
        float s = 0.f;
        #pragma unroll 8
        for (int o = 0; o < 64; ++o)
            s += w2[(k * 64 + o) * 25 + tap] * w1[o * 64 + i];
        g_Wc[(i * 25 + tap) * 9 + k] = s;
    }
    if (idx < 225) {
        int k = idx / 25, tap = idx % 25;
        float s = 0.f;
        #pragma unroll 8
        for (int o = 0; o < 64; ++o)
            s += w2[(k * 64 + o) * 25 + tap] * b1[o];
        g_bc[idx] = s;
    }
}

// ---------------- kernel C2: zero-pad-clipped bias field --------------------
__global__ void k_bfield() {
    int pix = blockIdx.x * blockDim.x + threadIdx.x;
    if (pix >= 16384) return;
    int h = pix >> 7, w = pix & 127;
    #pragma unroll
    for (int k = 0; k < 9; ++k) {
        float s = 0.f;
        for (int dy = 0; dy < 5; ++dy) {
            int ih = h + dy - 2;
            if (ih < 0 || ih > 127) continue;
            for (int dx = 0; dx < 5; ++dx) {
                int iw = w + dx - 2;
                if (iw < 0 || iw > 127) continue;
                s += g_bc[k * 25 + dy * 5 + dx];
            }
        }
        g_bfield[k * 16384 + pix] = s;
    }
}

// ---------------- kernel D: 5x5 conv (Cin=64 -> Cout=9), zero pad -----------
// Grid (4,8,8): 32x16 output tile per block; 128 threads (32,4); each thread
// owns 4 pixels x 9 output channels = 36 fp32 accumulators.
__global__ void __launch_bounds__(128) k_conv(const float* __restrict__ x) {
    __shared__ float sWc[8 * 225];      // 8 input channels x 25 taps x 9 k
    __shared__ float sX[8 * 20 * 36];   // 8 channels x (16+4) x (32+4)
    int tx = threadIdx.x, ty = threadIdx.y;
    int tid = ty * 32 + tx;
    int bx = blockIdx.x, by = blockIdx.y, bz = blockIdx.z;
    int h0 = by * 16, w0 = bx * 32;
    const float* xb = x + (size_t)bz * 64 * 16384;

    float acc[4][9];
    #pragma unroll
    for (int j = 0; j < 4; ++j)
        #pragma unroll
        for (int k = 0; k < 9; ++k) acc[j][k] = 0.f;

    for (int c0 = 0; c0 < 64; c0 += 8) {
        __syncthreads();
        // stage weights chunk (contiguous 1800 floats)
        for (int i = tid; i < 1800; i += 128) sWc[i] = g_Wc[c0 * 225 + i];
        // stage x tile: 8 x 20 x 36 with zero padding
        for (int i = tid; i < 5760; i += 128) {
            int c = i / 720, rem = i % 720;
            int y = rem / 36, xx = rem % 36;
            int gh = h0 + y - 2, gw = w0 + xx - 2;
            float v = 0.f;
            if (gh >= 0 && gh < 128 && gw >= 0 && gw < 128)
                v = xb[(size_t)(c0 + c) * 16384 + gh * 128 + gw];
            sX[i] = v;
        }
        __syncthreads();

        #pragma unroll 1
        for (int c = 0; c < 8; ++c) {
            const float* wbase = sWc + c * 225;
            const float* xbase = sX + c * 720;
            #pragma unroll 1
            for (int dy = 0; dy < 5; ++dy) {
                const float* wrow = wbase + dy * 45;
                const float* xrow = xbase + (ty + dy) * 36 + tx;
                #pragma unroll
                for (int dx = 0; dx < 5; ++dx) {
                    const float* wp = wrow + dx * 9;
                    float wv0 = wp[0], wv1 = wp[1], wv2 = wp[2], wv3 = wp[3],
                          wv4 = wp[4], wv5 = wp[5], wv6 = wp[6], wv7 = wp[7], wv8 = wp[8];
                    #pragma unroll
                    for (int j = 0; j < 4; ++j) {
                        float xv = xrow[4 * j * 36 + dx];
                        acc[j][0] = fmaf(wv0, xv, acc[j][0]);
                        acc[j][1] = fmaf(wv1, xv, acc[j][1]);
                        acc[j][2] = fmaf(wv2, xv, acc[j][2]);
                        acc[j][3] = fmaf(wv3, xv, acc[j][3]);
                        acc[j][4] = fmaf(wv4, xv, acc[j][4]);
                        acc[j][5] = fmaf(wv5, xv, acc[j][5]);
                        acc[j][6] = fmaf(wv6, xv, acc[j][6]);
                        acc[j][7] = fmaf(wv7, xv, acc[j][7]);
                        acc[j][8] = fmaf(wv8, xv, acc[j][8]);
                    }
                }
            }
        }
    }

    int w = w0 + tx;
    #pragma unroll
    for (int j = 0; j < 4; ++j) {
        int h = h0 + ty + 4 * j;
        int pix = h * 128 + w;
        #pragma unroll
        for (int k = 0; k < 9; ++k)
            g_wt[((size_t)bz * 9 + k) * 16384 + pix] = acc[j][k] + g_bfield[k * 16384 + pix];
    }
}

// ---------------- kernel E: softmax(wt_k * t_c) * 3x3 reflect patches -------
__global__ void __launch_bounds__(128) k_out(const float* __restrict__ x,
                                             float* __restrict__ out) {
    int w = threadIdx.x;       // 0..127
    int h = blockIdx.x;        // 0..127
    int b = blockIdx.y;        // 0..7
    int pix = h * 128 + w;

    float ak[9];
    float M = -1e30f;
    #pragma unroll
    for (int k = 0; k < 9; ++k) {
        ak[k] = g_wt[((size_t)b * 9 + k) * 16384 + pix];
        M = fmaxf(M, ak[k]);
    }
    #pragma unroll
    for (int k = 0; k < 9; ++k) ak[k] -= M;   // <= 0; t >= 0 so max preserved

    // reflect padding (PAD = 1, mode='reflect' -> -1 maps to 1, 128 to 126)
    int hm = (h == 0) ? 1 : h - 1;
    int hp = (h == 127) ? 126 : h + 1;
    int wm = (w == 0) ? 1 : w - 1;
    int wp = (w == 127) ? 126 : w + 1;
    int r0 = hm * 128, r1 = h * 128, r2 = hp * 128;

    const float* xb = x + (size_t)b * 64 * 16384;
    #pragma unroll 1
    for (int c = 0; c < 64; ++c) {
        const float* xc = xb + (size_t)c * 16384;
        float t = g_t[c];
        float p[9];
        p[0] = xc[r0 + wm]; p[1] = xc[r0 + w]; p[2] = xc[r0 + wp];
        p[3] = xc[r1 + wm]; p[4] = xc[r1 + w]; p[5] = xc[r1 + wp];
        p[6] = xc[r2 + wm]; p[7] = xc[r2 + w]; p[8] = xc[r2 + wp];
        float s = 0.f, o = 0.f;
        #pragma unroll
        for (int k = 0; k < 9; ++k) {
            float arg = ak[k] * t;   // t already includes log2(e)
            float e;
            asm("ex2.approx.ftz.f32 %0, %1;" : "=f"(e) : "f"(arg));
            s += e;
            o = fmaf(e, p[k], o);
        }
        out[(size_t)(b * 64 + c) * 16384 + pix] = __fdividef(o, s);
    }
}

// ---------------- launch ----------------------------------------------------
extern "C" void kernel_launch(void* const* d_in, const int* in_sizes, int n_in,
                              void* d_out, int out_size) {
    const float* x   = (const float*)d_in[0];
    const float* w1  = (const float*)d_in[1];
    const float* b1  = (const float*)d_in[2];
    const float* w2  = (const float*)d_in[3];
    const float* tc1 = (const float*)d_in[4];
    const float* tc2 = (const float*)d_in[5];
    float* out = (float*)d_out;
    (void)in_sizes; (void)n_in; (void)out_size;

    k_chansum<<<64, 256>>>(x);
    k_mlp<<<1, 64>>>(tc1, tc2);
    k_weights<<<(14400 + 255) / 256, 256>>>(w1, b1, w2);
    k_bfield<<<64, 256>>>();
    dim3 gc(4, 8, 8), bc(32, 4);
    k_conv<<<gc, bc>>>(x);
    dim3 ge(128, 8);
    k_out<<<ge, 128>>>(x, out);
}

// round 3
// speedup vs baseline: 1.2772x; 1.2772x over previous
#include <cuda_runtime.h>
#include <cstdint>

#define LOG2E 1.4426950408889634f

// ---------------- scratch (device globals; no allocations allowed) ----------
__device__ float g_part[8 * 64];            // per (b,c) partial sums
__device__ float g_t[64];                   // relu(MLP) * log2(e)
__device__ float g_Wc[64 * 25 * 10];        // composed weights [i][tap][k pad 10]
__device__ float g_bc[9 * 25];              // per-tap bias contribution [k][tap]
__device__ float g_bfield[9 * 128 * 128];   // clipped bias field [k][h][w]
__device__ float g_wt[8 * 9 * 128 * 128];   // conv logits [b][k][h][w]

// ---------------- f32x2 helpers ---------------------------------------------
__device__ __forceinline__ unsigned long long ld_s_b64(uint32_t addr) {
    unsigned long long v;
    asm volatile("ld.shared.b64 %0, [%1];" : "=l"(v) : "r"(addr));
    return v;
}
__device__ __forceinline__ unsigned long long pack2(float a) {
    unsigned long long v;
    unsigned int ai = __float_as_uint(a);
    asm("mov.b64 %0, {%1, %1};" : "=l"(v) : "r"(ai));
    return v;
}
__device__ __forceinline__ void fma2(unsigned long long& acc,
                                     unsigned long long a, unsigned long long b) {
    asm("fma.rn.f32x2 %0, %1, %2, %0;" : "+l"(acc) : "l"(a), "l"(b));
}

// ---------------- kernel A: per-(b,c) partial sums ---------------------------
__global__ void k_chansum(const float* __restrict__ x) {
    int c = blockIdx.x & 63;
    int b = blockIdx.x >> 6;
    int tid = threadIdx.x;   // 256
    const float4* p = (const float4*)(x + (size_t)(b * 64 + c) * 16384);
    float s = 0.f;
    #pragma unroll
    for (int i = tid; i < 4096; i += 256) {
        float4 v = p[i];
        s += v.x + v.y + v.z + v.w;
    }
    __shared__ float sh[256];
    sh[tid] = s;
    __syncthreads();
    for (int o = 128; o > 0; o >>= 1) {
        if (tid < o) sh[tid] += sh[tid + o];
        __syncthreads();
    }
    if (tid == 0) g_part[b * 64 + c] = sh[0];
}

// ---------------- kernel B: consensus MLP -> g_t ----------------------------
__global__ void k_mlp(const float* __restrict__ tc1, const float* __restrict__ tc2) {
    __shared__ float smean[64];
    __shared__ float sh1[16];
    int tid = threadIdx.x;  // 64 threads
    float s = 0.f;
    #pragma unroll
    for (int b = 0; b < 8; ++b) s += g_part[b * 64 + tid];
    smean[tid] = s * (1.f / 131072.f);
    __syncthreads();
    if (tid < 16) {
        float a = 0.f;
        #pragma unroll
        for (int c = 0; c < 64; ++c) a += tc1[tid * 64 + c] * smean[c];
        sh1[tid] = fmaxf(a, 0.f);
    }
    __syncthreads();
    float a = 0.f;
    #pragma unroll
    for (int j = 0; j < 16; ++j) a += tc2[tid * 16 + j] * sh1[j];
    g_t[tid] = fmaxf(a, 0.f) * LOG2E;
}

// ---------------- kernel C: compose 1x1 conv into 5x5 conv (k padded to 10) -
__global__ void k_weights(const float* __restrict__ w1, const float* __restrict__ b1,
                          const float* __restrict__ w2) {
    int idx = blockIdx.x * blockDim.x + threadIdx.x;
    if (idx < 16000) {
        int i = idx / 250, rem = idx % 250;
        int tap = rem / 10, k = rem % 10;
        float s = 0.f;
        if (k < 9) {
            #pragma unroll 8
            for (int o = 0; o < 64; ++o)
                s += w2[(k * 64 + o) * 25 + tap] * w1[o * 64 + i];
        }
        g_Wc[idx] = s;
    }
    if (idx < 225) {
        int k = idx / 25, tap = idx % 25;
        float s = 0.f;
        #pragma unroll 8
        for (int o = 0; o < 64; ++o)
            s += w2[(k * 64 + o) * 25 + tap] * b1[o];
        g_bc[idx] = s;
    }
}

// ---------------- kernel C2: zero-pad-clipped bias field --------------------
__global__ void k_bfield() {
    int idx = blockIdx.x * blockDim.x + threadIdx.x;   // over 9*16384
    if (idx >= 9 * 16384) return;
    int k = idx >> 14;
    int pix = idx & 16383;
    int h = pix >> 7, w = pix & 127;
    float s = 0.f;
    #pragma unroll
    for (int dy = 0; dy < 5; ++dy) {
        int ih = h + dy - 2;
        if (ih < 0 || ih > 127) continue;
        #pragma unroll
        for (int dx = 0; dx < 5; ++dx) {
            int iw = w + dx - 2;
            if (iw < 0 || iw > 127) continue;
            s += g_bc[k * 25 + dy * 5 + dx];
        }
    }
    g_bfield[idx] = s;
}

// ---------------- kernel D: 5x5 conv (Cin=64 -> Cout=9), f32x2 packed -------
// Grid (4,8,8): 32x16 output tile per block; 128 threads (32,4); each thread:
// 4 pixels x 5 k-pairs (k 0..9, last half is zero pad) of packed f32x2 accum.
__global__ void __launch_bounds__(128) k_conv(const float* __restrict__ x) {
    __shared__ __align__(16) float sWc[8 * 25 * 10];   // 8000 B, tap stride 40 B
    __shared__ __align__(16) float sX[8 * 20 * 36];    // 23040 B
    int tx = threadIdx.x, ty = threadIdx.y;
    int tid = ty * 32 + tx;
    int h0 = blockIdx.y * 16, w0 = blockIdx.x * 32;
    int bz = blockIdx.z;
    const float* xb = x + (size_t)bz * 64 * 16384;

    uint32_t sW_addr = (uint32_t)__cvta_generic_to_shared(sWc);
    uint32_t sX_addr = (uint32_t)__cvta_generic_to_shared(sX);

    unsigned long long acc[4][5];
    #pragma unroll
    for (int j = 0; j < 4; ++j)
        #pragma unroll
        for (int p = 0; p < 5; ++p) acc[j][p] = 0ull;

    for (int c0 = 0; c0 < 64; c0 += 8) {
        __syncthreads();
        // stage weight chunk (contiguous 2000 floats, pre-padded)
        for (int i = tid; i < 2000; i += 128) sWc[i] = g_Wc[c0 * 250 + i];
        // stage x tile: 8 x 20 x 36 with zero padding
        #pragma unroll 5
        for (int i = tid; i < 5760; i += 128) {
            int c = i / 720, rem = i % 720;
            int y = rem / 36, xx = rem % 36;
            int gh = h0 + y - 2, gw = w0 + xx - 2;
            float v = 0.f;
            if (gh >= 0 && gh < 128 && gw >= 0 && gw < 128)
                v = xb[(size_t)(c0 + c) * 16384 + gh * 128 + gw];
            sX[i] = v;
        }
        __syncthreads();

        #pragma unroll 1
        for (int c = 0; c < 8; ++c) {
            uint32_t wbase = sW_addr + c * 1000;               // 25 taps * 40 B
            uint32_t xbase = sX_addr + (c * 720 + ty * 36 + tx) * 4;
            #pragma unroll
            for (int dy = 0; dy < 5; ++dy) {
                uint32_t wrow = wbase + dy * 200;
                uint32_t xrow = xbase + dy * 144;              // 36 floats = 144 B
                #pragma unroll
                for (int dx = 0; dx < 5; ++dx) {
                    uint32_t wp = wrow + dx * 40;
                    unsigned long long wv0 = ld_s_b64(wp);
                    unsigned long long wv1 = ld_s_b64(wp + 8);
                    unsigned long long wv2 = ld_s_b64(wp + 16);
                    unsigned long long wv3 = ld_s_b64(wp + 24);
                    unsigned long long wv4 = ld_s_b64(wp + 32);
                    #pragma unroll
                    for (int j = 0; j < 4; ++j) {
                        // pixel row stride: 4 rows * 36 floats = 576 bytes
                        float xv;
                        asm volatile("ld.shared.f32 %0, [%1];"
                                     : "=f"(xv) : "r"(xrow + j * 576 + dx * 4));
                        unsigned long long xx = pack2(xv);
                        fma2(acc[j][0], wv0, xx);
                        fma2(acc[j][1], wv1, xx);
                        fma2(acc[j][2], wv2, xx);
                        fma2(acc[j][3], wv3, xx);
                        fma2(acc[j][4], wv4, xx);
                    }
                }
            }
        }
    }

    int w = w0 + tx;
    #pragma unroll
    for (int j = 0; j < 4; ++j) {
        int h = h0 + ty + 4 * j;
        int pix = h * 128 + w;
        float v[9];
        #pragma unroll
        for (int p = 0; p < 4; ++p) {
            v[2 * p]     = __uint_as_float((uint32_t)acc[j][p]);
            v[2 * p + 1] = __uint_as_float((uint32_t)(acc[j][p] >> 32));
        }
        v[8] = __uint_as_float((uint32_t)acc[j][4]);
        #pragma unroll
        for (int k = 0; k < 9; ++k)
            g_wt[((size_t)bz * 9 + k) * 16384 + pix] = v[k] + g_bfield[k * 16384 + pix];
    }
}

// ---------------- kernel E: softmax(wt_k * t_c) * 3x3 reflect patches -------
__global__ void __launch_bounds__(128) k_out(const float* __restrict__ x,
                                             float* __restrict__ out) {
    int w = threadIdx.x;       // 0..127
    int h = blockIdx.x;        // 0..127
    int b = blockIdx.y;        // 0..7
    int pix = h * 128 + w;

    float ak[9];
    float M = -1e30f;
    #pragma unroll
    for (int k = 0; k < 9; ++k) {
        ak[k] = g_wt[((size_t)b * 9 + k) * 16384 + pix];
        M = fmaxf(M, ak[k]);
    }
    #pragma unroll
    for (int k = 0; k < 9; ++k) ak[k] -= M;   // <= 0; t >= 0 so max preserved

    // reflect padding (PAD = 1): -1 -> 1, 128 -> 126
    int hm = (h == 0) ? 1 : h - 1;
    int hp = (h == 127) ? 126 : h + 1;
    int wm = (w == 0) ? 1 : w - 1;
    int wp = (w == 127) ? 126 : w + 1;
    int r0 = hm * 128, r1 = h * 128, r2 = hp * 128;

    const float* xb = x + (size_t)b * 64 * 16384;
    #pragma unroll 1
    for (int c = 0; c < 64; ++c) {
        const float* xc = xb + (size_t)c * 16384;
        float t = g_t[c];
        float p[9];
        p[0] = xc[r0 + wm]; p[1] = xc[r0 + w]; p[2] = xc[r0 + wp];
        p[3] = xc[r1 + wm]; p[4] = xc[r1 + w]; p[5] = xc[r1 + wp];
        p[6] = xc[r2 + wm]; p[7] = xc[r2 + w]; p[8] = xc[r2 + wp];
        float s = 0.f, o = 0.f;
        #pragma unroll
        for (int k = 0; k < 9; ++k) {
            float arg = ak[k] * t;   // t already includes log2(e)
            float e;
            asm("ex2.approx.ftz.f32 %0, %1;" : "=f"(e) : "f"(arg));
            s += e;
            o = fmaf(e, p[k], o);
        }
        out[(size_t)(b * 64 + c) * 16384 + pix] = __fdividef(o, s);
    }
}

// ---------------- launch ----------------------------------------------------
extern "C" void kernel_launch(void* const* d_in, const int* in_sizes, int n_in,
                              void* d_out, int out_size) {
    const float* x   = (const float*)d_in[0];
    const float* w1  = (const float*)d_in[1];
    const float* b1  = (const float*)d_in[2];
    const float* w2  = (const float*)d_in[3];
    const float* tc1 = (const float*)d_in[4];
    const float* tc2 = (const float*)d_in[5];
    float* out = (float*)d_out;
    (void)in_sizes; (void)n_in; (void)out_size;

    k_chansum<<<512, 256>>>(x);
    k_weights<<<63, 256>>>(w1, b1, w2);
    k_mlp<<<1, 64>>>(tc1, tc2);
    k_bfield<<<576, 256>>>();
    dim3 gc(4, 8, 8), bc(32, 4);
    k_conv<<<gc, bc>>>(x);
    dim3 ge(128, 8);
    k_out<<<ge, 128>>>(x, out);
}

// round 4
// speedup vs baseline: 1.2846x; 1.0058x over previous
#include <cuda_runtime.h>
#include <cstdint>

#define LOG2E 1.4426950408889634f

// ---------------- scratch (device globals; no allocations allowed) ----------
__device__ float g_part[8 * 64];            // per (b,c) partial sums
__device__ float g_t[64];                   // relu(MLP) * log2(e)
__device__ float g_Wc[64 * 25 * 10];        // composed weights [i][tap][k0..k7,{k8,k8}]
__device__ float g_bc[9 * 25];              // per-tap bias contribution [k][tap]
__device__ float g_bfield[9 * 128 * 128];   // clipped bias field [k][h][w]
__device__ float g_wt[8 * 9 * 128 * 128];   // conv logits [b][k][h][w]

// ---------------- f32x2 helpers ---------------------------------------------
__device__ __forceinline__ unsigned long long ld_s_b64(uint32_t addr) {
    unsigned long long v;
    asm volatile("ld.shared.b64 %0, [%1];" : "=l"(v) : "r"(addr));
    return v;
}
__device__ __forceinline__ void st_s_dup(uint32_t addr, float v) {
    asm volatile("st.shared.v2.f32 [%0], {%1, %2};" :: "r"(addr), "f"(v), "f"(v));
}
__device__ __forceinline__ void fma2(unsigned long long& acc,
                                     unsigned long long a, unsigned long long b) {
    asm("fma.rn.f32x2 %0, %1, %2, %0;" : "+l"(acc) : "l"(a), "l"(b));
}
__device__ __forceinline__ unsigned long long pack_ab(unsigned long long a,
                                                      unsigned long long b) {
    unsigned long long v;
    asm("mov.b64 %0, {%1, %2};" : "=l"(v)
        : "r"((uint32_t)a), "r"((uint32_t)b));
    return v;
}

// ---------------- P1: chansum (blocks 0..511) + compose weights (512..574) --
__global__ void k_prep1(const float* __restrict__ x, const float* __restrict__ w1,
                        const float* __restrict__ b1, const float* __restrict__ w2) {
    int blk = blockIdx.x;
    int tid = threadIdx.x;   // 256
    if (blk < 512) {
        int c = blk & 63, b = blk >> 6;
        const float4* p = (const float4*)(x + (size_t)(b * 64 + c) * 16384);
        float s = 0.f;
        for (int i = tid; i < 4096; i += 256) {
            float4 v = p[i];
            s += v.x + v.y + v.z + v.w;
        }
        __shared__ float sh[256];
        sh[tid] = s;
        __syncthreads();
        for (int o = 128; o > 0; o >>= 1) {
            if (tid < o) sh[tid] += sh[tid + o];
            __syncthreads();
        }
        if (tid == 0) g_part[b * 64 + c] = sh[0];
    } else {
        int idx = (blk - 512) * 256 + tid;       // 0..16127
        if (idx < 16000) {
            int i = idx / 250, rem = idx % 250;
            int tap = rem / 10, k = rem % 10;
            int kk = (k >= 8) ? 8 : k;           // slot 9 duplicates k8
            float s = 0.f;
            #pragma unroll 8
            for (int o = 0; o < 64; ++o)
                s += w2[(kk * 64 + o) * 25 + tap] * w1[o * 64 + i];
            g_Wc[idx] = s;
        }
        if (idx < 225) {
            int k = idx / 25, tap = idx % 25;
            float s = 0.f;
            #pragma unroll 8
            for (int o = 0; o < 64; ++o)
                s += w2[(k * 64 + o) * 25 + tap] * b1[o];
            g_bc[idx] = s;
        }
    }
}

// ---------------- P2: bfield (blocks 0..63) + MLP (block 64) ----------------
__global__ void k_prep2(const float* __restrict__ tc1, const float* __restrict__ tc2) {
    int blk = blockIdx.x;
    int tid = threadIdx.x;   // 256
    if (blk == 64) {
        __shared__ float smean[64];
        __shared__ float sh1[16];
        if (tid < 64) {
            float s = 0.f;
            #pragma unroll
            for (int b = 0; b < 8; ++b) s += g_part[b * 64 + tid];
            smean[tid] = s * (1.f / 131072.f);
        }
        __syncthreads();
        if (tid < 16) {
            float a = 0.f;
            #pragma unroll
            for (int c = 0; c < 64; ++c) a += tc1[tid * 64 + c] * smean[c];
            sh1[tid] = fmaxf(a, 0.f);
        }
        __syncthreads();
        if (tid < 64) {
            float a = 0.f;
            #pragma unroll
            for (int j = 0; j < 16; ++j) a += tc2[tid * 16 + j] * sh1[j];
            g_t[tid] = fmaxf(a, 0.f) * LOG2E;
        }
        return;
    }
    __shared__ float sbc[225];
    if (tid < 225) sbc[tid] = g_bc[tid];
    __syncthreads();
    int pix = blk * 256 + tid;
    int h = pix >> 7, w = pix & 127;
    #pragma unroll
    for (int k = 0; k < 9; ++k) {
        float s = 0.f;
        #pragma unroll
        for (int dy = 0; dy < 5; ++dy) {
            int ih = h + dy - 2;
            if (ih < 0 || ih > 127) continue;
            #pragma unroll
            for (int dx = 0; dx < 5; ++dx) {
                int iw = w + dx - 2;
                if (iw < 0 || iw > 127) continue;
                s += sbc[k * 25 + dy * 5 + dx];
            }
        }
        g_bfield[k * 16384 + pix] = s;
    }
}

// ---------------- kernel D: 5x5 conv (Cin=64 -> Cout=9), f32x2, dup-X -------
// Dynamic smem: [0, 8000) sWc floats; [8000, 54080) sX duplicated pairs.
// Grid (4,8,8): 32x16 tile; 128 threads (32,4); 4 px x 9 k per thread.
__global__ void __launch_bounds__(128) k_conv(const float* __restrict__ x) {
    extern __shared__ float sdyn[];
    int tx = threadIdx.x, ty = threadIdx.y;
    int tid = ty * 32 + tx;
    int h0 = blockIdx.y * 16, w0 = blockIdx.x * 32;
    int bz = blockIdx.z;
    const float* xb = x + (size_t)bz * 64 * 16384;

    uint32_t sbase = (uint32_t)__cvta_generic_to_shared(sdyn);
    uint32_t sW = sbase;             // 2000 floats
    uint32_t sX = sbase + 8000;      // 5760 pairs (8 B each)

    unsigned long long acc[4][4];    // [px j][k-pair 0..3] = k0..7
    unsigned long long acc8[2];      // [jp] = {k8@px2jp, k8@px2jp+1}
    #pragma unroll
    for (int j = 0; j < 4; ++j)
        #pragma unroll
        for (int p = 0; p < 4; ++p) acc[j][p] = 0ull;
    acc8[0] = acc8[1] = 0ull;

    for (int c0 = 0; c0 < 64; c0 += 8) {
        __syncthreads();
        // stage weight chunk (contiguous 2000 floats, k8 pre-duplicated)
        for (int i = tid; i < 2000; i += 128)
            sdyn[i] = g_Wc[c0 * 250 + i];
        // stage x tile as duplicated pairs: 8 ch x 20 x 36
        #pragma unroll 5
        for (int i = tid; i < 5760; i += 128) {
            int c = i / 720, rem = i % 720;
            int y = rem / 36, xx = rem % 36;
            int gh = h0 + y - 2, gw = w0 + xx - 2;
            float v = 0.f;
            if (gh >= 0 && gh < 128 && gw >= 0 && gw < 128)
                v = xb[(size_t)(c0 + c) * 16384 + gh * 128 + gw];
            st_s_dup(sX + i * 8, v);
        }
        __syncthreads();

        #pragma unroll 1
        for (int c = 0; c < 8; ++c) {
            uint32_t wbase = sW + c * 1000;                    // 25 taps * 40 B
            uint32_t xbase = sX + (c * 720 + ty * 36 + tx) * 8;
            #pragma unroll
            for (int dy = 0; dy < 5; ++dy) {
                uint32_t wrow = wbase + dy * 200;
                uint32_t xrow = xbase + dy * 288;              // 36 pairs
                #pragma unroll
                for (int dx = 0; dx < 5; ++dx) {
                    uint32_t wp = wrow + dx * 40;
                    unsigned long long wv0 = ld_s_b64(wp);
                    unsigned long long wv1 = ld_s_b64(wp + 8);
                    unsigned long long wv2 = ld_s_b64(wp + 16);
                    unsigned long long wv3 = ld_s_b64(wp + 24);
                    unsigned long long wv8 = ld_s_b64(wp + 32);   // {k8,k8}
                    #pragma unroll
                    for (int jp = 0; jp < 2; ++jp) {
                        // px rows: 2jp and 2jp+1 (stride 4 rows = 1152 B)
                        unsigned long long xa = ld_s_b64(xrow + (2 * jp) * 1152 + dx * 8);
                        unsigned long long xb2 = ld_s_b64(xrow + (2 * jp + 1) * 1152 + dx * 8);
                        fma2(acc[2 * jp][0], wv0, xa);
                        fma2(acc[2 * jp][1], wv1, xa);
                        fma2(acc[2 * jp][2], wv2, xa);
                        fma2(acc[2 * jp][3], wv3, xa);
                        fma2(acc[2 * jp + 1][0], wv0, xb2);
                        fma2(acc[2 * jp + 1][1], wv1, xb2);
                        fma2(acc[2 * jp + 1][2], wv2, xb2);
                        fma2(acc[2 * jp + 1][3], wv3, xb2);
                        fma2(acc8[jp], wv8, pack_ab(xa, xb2));
                    }
                }
            }
        }
    }

    int w = w0 + tx;
    #pragma unroll
    for (int j = 0; j < 4; ++j) {
        int h = h0 + ty + 4 * j;
        int pix = h * 128 + w;
        float v[9];
        #pragma unroll
        for (int p = 0; p < 4; ++p) {
            v[2 * p]     = __uint_as_float((uint32_t)acc[j][p]);
            v[2 * p + 1] = __uint_as_float((uint32_t)(acc[j][p] >> 32));
        }
        unsigned long long a8 = acc8[j >> 1];
        v[8] = (j & 1) ? __uint_as_float((uint32_t)(a8 >> 32))
                       : __uint_as_float((uint32_t)a8);
        #pragma unroll
        for (int k = 0; k < 9; ++k)
            g_wt[((size_t)bz * 9 + k) * 16384 + pix] = v[k] + g_bfield[k * 16384 + pix];
    }
}

// ---------------- kernel E: softmax(wt_k * t_c) * 3x3 reflect patches -------
__global__ void __launch_bounds__(128) k_out(const float* __restrict__ x,
                                             float* __restrict__ out) {
    __shared__ float st[64];
    int w = threadIdx.x;       // 0..127
    int h = blockIdx.x;        // 0..127
    int b = blockIdx.y;        // 0..7
    int pix = h * 128 + w;
    if (w < 64) st[w] = g_t[w];
    __syncthreads();

    float ak[9];
    float M = -1e30f;
    #pragma unroll
    for (int k = 0; k < 9; ++k) {
        ak[k] = g_wt[((size_t)b * 9 + k) * 16384 + pix];
        M = fmaxf(M, ak[k]);
    }
    #pragma unroll
    for (int k = 0; k < 9; ++k) ak[k] -= M;   // <= 0; t >= 0 so max preserved

    // reflect padding (PAD = 1): -1 -> 1, 128 -> 126
    int hm = (h == 0) ? 1 : h - 1;
    int hp = (h == 127) ? 126 : h + 1;
    int wm = (w == 0) ? 1 : w - 1;
    int wp = (w == 127) ? 126 : w + 1;
    int r0 = hm * 128, r1 = h * 128, r2 = hp * 128;

    const float* xb = x + (size_t)b * 64 * 16384;
    #pragma unroll 1
    for (int c = 0; c < 64; ++c) {
        const float* xc = xb + (size_t)c * 16384;
        float t = st[c];
        float p[9];
        p[0] = xc[r0 + wm]; p[1] = xc[r0 + w]; p[2] = xc[r0 + wp];
        p[3] = xc[r1 + wm]; p[4] = xc[r1 + w]; p[5] = xc[r1 + wp];
        p[6] = xc[r2 + wm]; p[7] = xc[r2 + w]; p[8] = xc[r2 + wp];
        float o;
        if (t == 0.f) {
            // exp(0)=1 for all 9 taps: exactly uniform attention
            float s9 = ((p[0] + p[1]) + (p[2] + p[3])) + ((p[4] + p[5]) + (p[6] + p[7])) + p[8];
            o = s9 * (1.f / 9.f);
        } else {
            float s = 0.f, oo = 0.f;
            #pragma unroll
            for (int k = 0; k < 9; ++k) {
                float arg = ak[k] * t;   // t includes log2(e)
                float e;
                asm("ex2.approx.ftz.f32 %0, %1;" : "=f"(e) : "f"(arg));
                s += e;
                oo = fmaf(e, p[k], oo);
            }
            o = __fdividef(oo, s);
        }
        out[(size_t)(b * 64 + c) * 16384 + pix] = o;
    }
}

// ---------------- launch ----------------------------------------------------
extern "C" void kernel_launch(void* const* d_in, const int* in_sizes, int n_in,
                              void* d_out, int out_size) {
    const float* x   = (const float*)d_in[0];
    const float* w1  = (const float*)d_in[1];
    const float* b1  = (const float*)d_in[2];
    const float* w2  = (const float*)d_in[3];
    const float* tc1 = (const float*)d_in[4];
    const float* tc2 = (const float*)d_in[5];
    float* out = (float*)d_out;
    (void)in_sizes; (void)n_in; (void)out_size;

    static bool attr_set = false;
    if (!attr_set) {
        cudaFuncSetAttribute(k_conv, cudaFuncAttributeMaxDynamicSharedMemorySize, 54080);
        attr_set = true;
    }

    k_prep1<<<575, 256>>>(x, w1, b1, w2);
    k_prep2<<<65, 256>>>(tc1, tc2);
    dim3 gc(4, 8, 8), bc(32, 4);
    k_conv<<<gc, bc, 54080>>>(x);
    dim3 ge(128, 8);
    k_out<<<ge, 128>>>(x, out);
}